// round 16
// baseline (speedup 1.0000x reference)
#include <cuda_runtime.h>
#include <cuda_bf16.h>
#include <cstdint>

#define Tlen  8192
#define Bsz   4
#define RES   256
#define SKIPC 512
#define NCLSC 256
#define NLAY  30
#define WIN   3072
#define HSTR  3200

// ---------------- device scratch (allocation-free) ----------------
__device__ float g_h[2][Bsz][RES][HSTR];                 // ping-pong hidden state; pads zero
__device__ uint32_t g_Ad[(size_t)NLAY * 16 * 2 * 2 * 2048];  // conv A fragments  [lay][c32][s][hi/lo][2048]
__device__ uint32_t g_Ar[(size_t)NLAY * 8  * 2 * 2 * 2048];  // resid A fragments
__device__ float g_gLast[NLAY][Bsz][RES];
__device__ float g_skip[Bsz][SKIPC];

// ---------------- helpers ----------------
__device__ __forceinline__ uint32_t su32(const void* p) {
    return (uint32_t)__cvta_generic_to_shared(p);
}
__device__ __forceinline__ uint32_t pk2b(__nv_bfloat16 a, __nv_bfloat16 b) {
    __nv_bfloat162 v; v.x = a; v.y = b;
    return *(uint32_t*)&v;
}
__device__ __forceinline__ float gate_fn(float d) {
    float e1 = __expf(-d);
    float sg = __fdividef(1.f, 1.f + e1);
    float th = __fdividef(2.f, 1.f + e1 * e1) - 1.f;
    return th * sg;
}
__device__ __forceinline__ void hmma(float* d, const uint32_t* a, uint32_t b0, uint32_t b1) {
    asm volatile(
        "mma.sync.aligned.m16n8k16.row.col.f32.bf16.bf16.f32 "
        "{%0,%1,%2,%3}, {%4,%5,%6,%7}, {%8,%9}, {%0,%1,%2,%3};"
        : "+f"(d[0]), "+f"(d[1]), "+f"(d[2]), "+f"(d[3])
        : "r"(a[0]), "r"(a[1]), "r"(a[2]), "r"(a[3]), "r"(b0), "r"(b1));
}

#define CPA16(d, s) asm volatile("cp.async.cg.shared.global [%0],[%1],16;\n" :: "r"(d), "l"(s))
#define CPCOMMIT()  asm volatile("cp.async.commit_group;\n")
#define CPWAIT0()   asm volatile("cp.async.wait_group 0;\n" ::: "memory")

// ---------------- prep: weights -> bf16 hi/lo, A-fragment order ----------------
__global__ void prep_w(const float* __restrict__ W, uint32_t* __restrict__ dst, int conv) {
    int c16 = blockIdx.x, lay = blockIdx.y;
    int tid = threadIdx.x;
    int mt = tid >> 5, L = tid & 31, g = L >> 2, t = L & 3;
    uint32_t hi[4], lo[4];
#pragma unroll
    for (int r = 0; r < 4; r++) {
        int mm = mt * 16 + g + (r & 1) * 8;
        int kb = 2 * t + (r >> 1) * 8;
        float f0, f1;
        if (conv) {
            int tap = c16 >> 4;
            int ci  = (c16 & 15) * 16 + kb;
            const float* p = W + (((size_t)lay * 256 + mm) * 256 + ci) * 2 + tap;
            f0 = p[0]; f1 = p[2];
        } else {
            int k = c16 * 16 + kb;
            const float* p = W + ((size_t)lay * 256 + mm) * 256 + k;
            f0 = p[0]; f1 = p[1];
        }
        __nv_bfloat16 h0 = __float2bfloat16(f0), h1 = __float2bfloat16(f1);
        hi[r] = pk2b(h0, h1);
        lo[r] = pk2b(__float2bfloat16(f0 - __bfloat162float(h0)),
                     __float2bfloat16(f1 - __bfloat162float(h1)));
    }
    int K32 = conv ? 16 : 8;
    int c32 = c16 >> 1, s = c16 & 1;
    size_t base = ((((size_t)lay * K32 + c32) * 2 + s) * 2) * 2048 + (size_t)(mt * 32 + L) * 4;
#pragma unroll
    for (int r = 0; r < 4; r++) { dst[base + r] = hi[r]; dst[base + 2048 + r] = lo[r]; }
}

// ---------------- start conv ----------------
__global__ void start_conv(const float* __restrict__ x, const float* __restrict__ Wst,
                           const float* __restrict__ bst) {
    int b = blockIdx.y;
    int u = blockIdx.x * 256 + threadIdx.x;
    int t = (Tlen - WIN) + u;
    float x0 = x[b * Tlen + t - 1], x1 = x[b * Tlen + t];
    for (int c = 0; c < RES; c++)
        g_h[0][b][c][u] = bst[c] + Wst[2 * c] * x0 + Wst[2 * c + 1] * x1;
}

// ---------------- fused HMMA layer ----------------
// 512 thr = 16 warps: wr=warp>>2 (M 64-slice), wc=warp&3 (N slice of NT ntiles). BN = 32*NT.
// PB = batches per block (A staging, barriers, A-fragment LDS shared across batches).
template <int NT, int PB>
__global__ void __launch_bounds__(512, 1)
layer_mma(int pp, int layer, int dil, int u0,
          const uint32_t* __restrict__ Ac, const uint32_t* __restrict__ Ar,
          const float* __restrict__ bd, const float* __restrict__ br) {
    constexpr int NTB   = 4 * NT;
    constexpr int BN    = 8 * NTB;
    constexpr int NEL   = NT;                  // B elements per thread per chunk per batch
    constexpr int BUFSZ = 256 * NTB;           // u32 per (pb,buf) B buffer
    constexpr int GSZ   = 2048 * NTB;          // u32 gs per batch
    constexpr int BSOFF = 16384;
    constexpr int GSOFF = BSOFF + PB * 2 * BUFSZ;

    extern __shared__ uint32_t sm[];
    const int tid = threadIdx.x, L = tid & 31, w = tid >> 5;
    const int wr = w >> 2, wc = w & 3, g = L >> 2, t = L & 3;
    const int b0 = blockIdx.y * PB;
    const int ub = u0 + blockIdx.x * BN;

    const float* hin[PB];
    float*       hout[PB];
#pragma unroll
    for (int pb = 0; pb < PB; pb++) {
        hin[pb]  = &g_h[pp][b0 + pb][0][0];
        hout[pb] = &g_h[pp ^ 1][b0 + pb][0][0];
    }

    float acc[PB][4][NT][4];
#pragma unroll
    for (int pb = 0; pb < PB; pb++)
#pragma unroll
        for (int mt = 0; mt < 4; mt++)
#pragma unroll
            for (int nl = 0; nl < NT; nl++)
#pragma unroll
                for (int e = 0; e < 4; e++) acc[pb][mt][nl][e] = 0.f;

    float rb0[PB][NEL], rb1[PB][NEL];     // raw B values held across compute

    auto stageA = [&](int buf, const uint32_t* src) {   // 8192 u32 contiguous
        uint32_t* dstb = sm + buf * 8192;
        for (int i = tid; i < 2048; i += 512)
            CPA16(su32(dstb + 4 * i), src + 4 * i);
    };
    // issue raw B global loads for conv chunk c (register destination, no stall)
    auto loadB = [&](int c) {
        int tap = c >> 3;
        int off = tap ? 0 : dil;
        int cibase = (c * 32) & 255;
#pragma unroll
        for (int pb = 0; pb < PB; pb++)
#pragma unroll
            for (int it = 0; it < NEL; it++) {
                int e = tid + it * 512;
                int LL = e & 31, x = e >> 5;
                int nt = x % NTB, y = x / NTB;
                int r = y & 1, s = y >> 1;
                int gg = LL >> 2, tt = LL & 3;
                int kk = 2 * tt + r * 8;
                int ci = cibase + s * 16 + kk;
                const float* p = hin[pb] + (size_t)ci * HSTR + (ub + nt * 8 + gg - off);
                rb0[pb][it] = p[0];
                rb1[pb][it] = p[HSTR];
            }
    };
    // convert held raw values -> bf16 hi/lo fragments (STS), data long arrived
    auto storeB = [&](int buf) {
#pragma unroll
        for (int pb = 0; pb < PB; pb++)
#pragma unroll
            for (int it = 0; it < NEL; it++) {
                int e = tid + it * 512;
                int LL = e & 31, x = e >> 5;
                int nt = x % NTB, y = x / NTB;
                int r = y & 1, s = y >> 1;
                float f0 = rb0[pb][it], f1 = rb1[pb][it];
                __nv_bfloat16 h0 = __float2bfloat16(f0), h1 = __float2bfloat16(f1);
                int base = BSOFF + (pb * 2 + buf) * BUFSZ;
                sm[base + (((s * 2 + 0) * NTB + nt) * 32 + LL) * 2 + r] = pk2b(h0, h1);
                sm[base + (((s * 2 + 1) * NTB + nt) * 32 + LL) * 2 + r] =
                    pk2b(__float2bfloat16(f0 - __bfloat162float(h0)),
                         __float2bfloat16(f1 - __bfloat162float(h1)));
            }
    };

    // compute one k32 chunk for ALL batches; A fragments shared across pb
    auto compute = [&](int buf, int phase, int kt0) {
#pragma unroll
        for (int s = 0; s < 2; s++) {
            uint4 ah[4], al[4];
            const uint32_t* Abase = sm + (buf * 2 + s) * 2 * 2048;
#pragma unroll
            for (int mt = 0; mt < 4; mt++) {
                int gmt = wr * 4 + mt;
                ah[mt] = *(const uint4*)(Abase + (gmt * 32 + L) * 4);
                al[mt] = *(const uint4*)(Abase + 2048 + (gmt * 32 + L) * 4);
            }
#pragma unroll
            for (int pb = 0; pb < PB; pb++) {
                int B0 = (phase == 0) ? (BSOFF + (pb * 2 + buf) * BUFSZ) : (GSOFF + pb * GSZ);
                int rr = (phase == 0) ? s : (kt0 + s);
#pragma unroll
                for (int nl = 0; nl < NT; nl++) {
                    int nt = wc * NT + nl;
                    int ih = B0 + (((rr * 2 + 0) * NTB + nt) * 32 + L) * 2;
                    int il = B0 + (((rr * 2 + 1) * NTB + nt) * 32 + L) * 2;
                    uint32_t bh0 = sm[ih], bh1 = sm[ih + 1];
                    uint32_t bl0 = sm[il], bl1 = sm[il + 1];
#pragma unroll
                    for (int mt = 0; mt < 4; mt++) {
                        hmma(acc[pb][mt][nl], (const uint32_t*)&ah[mt], bh0, bh1);
                        hmma(acc[pb][mt][nl], (const uint32_t*)&al[mt], bh0, bh1);
                        hmma(acc[pb][mt][nl], (const uint32_t*)&ah[mt], bl0, bl1);
                    }
                }
            }
        }
    };

    // ---- prologue: chunk 0 fully staged ----
    stageA(0, Ac); CPCOMMIT();
    loadB(0);
    storeB(0);            // one-time exposed latency
    int buf = 0;
    // ---- phase 1: conv GEMM, 16 k32 chunks ----
    for (int c = 0; c < 16; c++) {
        CPWAIT0(); __syncthreads();          // A(c) landed; B(c) STS visible
        if (c + 1 < 16) {
            loadB(c + 1);                    // issue LDGs now, consume after compute
            stageA(buf ^ 1, Ac + (size_t)(c + 1) * 8192);
        } else {
            stageA(buf ^ 1, Ar);             // prefetch phase-2 chunk 0
        }
        CPCOMMIT();
        compute(buf, 0, 0);                  // hides the B LDG latency
        if (c + 1 < 16) storeB(buf ^ 1);     // convert + STS (data arrived)
        buf ^= 1;
    }

    // ---- gate: acc -> gs (phase-2 B fragments, bf16 hi/lo) ----
#pragma unroll
    for (int pb = 0; pb < PB; pb++)
#pragma unroll
        for (int mt = 0; mt < 4; mt++)
#pragma unroll
            for (int nl = 0; nl < NT; nl++)
#pragma unroll
                for (int e = 0; e < 4; e++) {
                    int mm = wr * 64 + mt * 16 + g + (e >> 1) * 8;
                    int n  = wc * NT * 8 + nl * 8 + 2 * t + (e & 1);
                    float gv = gate_fn(acc[pb][mt][nl][e] + bd[mm]);
                    if (ub + n == WIN - 1) g_gLast[layer][b0 + pb][mm] = gv;
                    __nv_bfloat16 hh = __float2bfloat16(gv);
                    __nv_bfloat16 ll = __float2bfloat16(gv - __bfloat162float(hh));
                    int kt2 = mm >> 4, kk2 = mm & 15;
                    int r2 = kk2 >> 3, t2 = (kk2 & 7) >> 1, hp = kk2 & 1;
                    int L2 = (n & 7) * 4 + t2;
                    int nt2 = n >> 3;
                    int base = GSOFF + pb * GSZ;
                    int ih = base + (((kt2 * 2 + 0) * NTB + nt2) * 32 + L2) * 2 + r2;
                    int il = base + (((kt2 * 2 + 1) * NTB + nt2) * 32 + L2) * 2 + r2;
                    ((__nv_bfloat16*)&sm[ih])[hp] = hh;
                    ((__nv_bfloat16*)&sm[il])[hp] = ll;
                    acc[pb][mt][nl][e] = 0.f;
                }

    // ---- phase 2: residual GEMM, 8 k32 chunks, B = gs ----
    for (int c = 0; c < 8; c++) {
        CPWAIT0(); __syncthreads();      // also publishes gs before first read
        if (c + 1 < 8) stageA(buf ^ 1, Ar + (size_t)(c + 1) * 8192);
        CPCOMMIT();
        compute(buf, 1, c * 2);
        buf ^= 1;
    }

    // ---- residual epilogue ----
#pragma unroll
    for (int pb = 0; pb < PB; pb++)
#pragma unroll
        for (int mt = 0; mt < 4; mt++)
#pragma unroll
            for (int nl = 0; nl < NT; nl++)
#pragma unroll
                for (int e = 0; e < 4; e++) {
                    int mm = wr * 64 + mt * 16 + g + (e >> 1) * 8;
                    int n  = wc * NT * 8 + nl * 8 + 2 * t + (e & 1);
                    int uu = ub + n;
                    if (uu < WIN)
                        hout[pb][(size_t)mm * HSTR + uu] =
                            hin[pb][(size_t)mm * HSTR + uu] + acc[pb][mt][nl][e] + br[mm];
                }
}

// ---------------- skip head ----------------
__global__ void skip_kernel(const float* __restrict__ Ws, const float* __restrict__ bs) {
    int b = blockIdx.x;
    int w = threadIdx.x >> 5, lane = threadIdx.x & 31;
    int so_base = blockIdx.y * 64 + w * 8;
    for (int oi = 0; oi < 8; oi++) {
        int so = so_base + oi;
        float v = (lane < NLAY) ? bs[lane * SKIPC + so] : 0.f;
        for (int l = 0; l < NLAY; l++) {
            const float* wr = Ws + ((size_t)l * SKIPC + so) * RES;
            const float* gg = &g_gLast[l][b][0];
#pragma unroll
            for (int k = lane; k < RES; k += 32) v += wr[k] * gg[k];
        }
#pragma unroll
        for (int s = 16; s; s >>= 1) v += __shfl_xor_sync(0xffffffffu, v, s);
        if (lane == 0) g_skip[b][so] = fmaxf(v, 0.f);
    }
}

// ---------------- end head ----------------
__global__ void end_kernel(const float* __restrict__ We1, const float* __restrict__ be1,
                           const float* __restrict__ We2, const float* __restrict__ be2,
                           float* __restrict__ out) {
    __shared__ float sk[SKIPC];
    __shared__ float mid[SKIPC];
    int b = blockIdx.x, tid = threadIdx.x;
    int w = tid >> 5, lane = tid & 31;
    for (int i = tid; i < SKIPC; i += 256) sk[i] = g_skip[b][i];
    __syncthreads();
    for (int oi = 0; oi < 64; oi++) {
        int so = w * 64 + oi;
        const float* row = We1 + (size_t)so * SKIPC;
        float v = 0.f;
#pragma unroll
        for (int k = lane; k < SKIPC; k += 32) v += row[k] * sk[k];
#pragma unroll
        for (int s = 16; s; s >>= 1) v += __shfl_xor_sync(0xffffffffu, v, s);
        if (lane == 0) mid[so] = fmaxf(v + be1[so], 0.f);
    }
    __syncthreads();
    for (int oi = 0; oi < 32; oi++) {
        int nc = w * 32 + oi;
        const float* row = We2 + (size_t)nc * SKIPC;
        float v = 0.f;
#pragma unroll
        for (int k = lane; k < SKIPC; k += 32) v += row[k] * mid[k];
#pragma unroll
        for (int s = 16; s; s >>= 1) v += __shfl_xor_sync(0xffffffffu, v, s);
        if (lane == 0) out[b * NCLSC + nc] = v + be2[nc];
    }
}

// ---------------- host ----------------
static const int DILS[NLAY] = {1,2,4,8,16,32,64,128,256,512,
                               1,2,4,8,16,32,64,128,256,512,
                               1,2,4,8,16,32,64,128,256,512};

static inline size_t smem_for(int NT, int PB) {
    int NTB = 4 * NT;
    return (size_t)(16384 + (size_t)PB * 2 * 256 * NTB + (size_t)PB * 2048 * NTB) * 4;
}

extern "C" void kernel_launch(void* const* d_in, const int* in_sizes, int n_in,
                              void* d_out, int out_size) {
    (void)in_sizes; (void)n_in; (void)out_size;
    const float* x   = (const float*)d_in[0];
    const float* Wst = (const float*)d_in[1];
    const float* bst = (const float*)d_in[2];
    const float* Wd  = (const float*)d_in[3];
    const float* bd  = (const float*)d_in[4];
    const float* Wr  = (const float*)d_in[5];
    const float* br  = (const float*)d_in[6];
    const float* Ws  = (const float*)d_in[7];
    const float* bs  = (const float*)d_in[8];
    const float* We1 = (const float*)d_in[9];
    const float* be1 = (const float*)d_in[10];
    const float* We2 = (const float*)d_in[11];
    const float* be2 = (const float*)d_in[12];
    float* out = (float*)d_out;

    cudaFuncSetAttribute((const void*)layer_mma<3, 1>, cudaFuncAttributeMaxDynamicSharedMemorySize, (int)smem_for(3, 1));
    cudaFuncSetAttribute((const void*)layer_mma<2, 1>, cudaFuncAttributeMaxDynamicSharedMemorySize, (int)smem_for(2, 1));
    cudaFuncSetAttribute((const void*)layer_mma<1, 2>, cudaFuncAttributeMaxDynamicSharedMemorySize, (int)smem_for(1, 2));

    uint32_t *ad_dev, *ar_dev;
    cudaGetSymbolAddress((void**)&ad_dev, g_Ad);
    cudaGetSymbolAddress((void**)&ar_dev, g_Ar);

    prep_w<<<dim3(32, NLAY), 512>>>(Wd, ad_dev, 1);
    prep_w<<<dim3(16, NLAY), 512>>>(Wr, ar_dev, 0);
    start_conv<<<dim3(WIN / 256, Bsz), 256>>>(x, Wst, bst);

    int suf[NLAY + 1];
    suf[NLAY] = 0;
    for (int i = NLAY - 1; i >= 0; i--) suf[i] = suf[i + 1] + DILS[i];

    for (int i = 0; i < NLAY; i++) {
        int N  = 1 + suf[i + 1];
        int u0 = WIN - N;
        int pp = i & 1;
        const uint32_t* ac = ad_dev + (size_t)i * 16 * 8192;
        const uint32_t* ar = ar_dev + (size_t)i * 8 * 8192;
        const float* bdp = bd + (size_t)i * RES;
        const float* brp = br + (size_t)i * RES;

        if (N > 2368) {
            int gx = (N + 95) / 96;
            layer_mma<3, 1><<<dim3(gx, Bsz), 512, smem_for(3, 1)>>>(pp, i, DILS[i], u0, ac, ar, bdp, brp);
        } else if (N > 1184) {
            int gx = (N + 63) / 64;
            layer_mma<2, 1><<<dim3(gx, Bsz), 512, smem_for(2, 1)>>>(pp, i, DILS[i], u0, ac, ar, bdp, brp);
        } else {
            int gx = (N + 31) / 32;
            layer_mma<1, 2><<<dim3(gx, Bsz / 2), 512, smem_for(1, 2)>>>(pp, i, DILS[i], u0, ac, ar, bdp, brp);
        }
    }

    skip_kernel<<<dim3(Bsz, SKIPC / 64), 256>>>(Ws, bs);
    end_kernel<<<Bsz, 256>>>(We1, be1, We2, be2, out);
}

// round 17
// speedup vs baseline: 1.1136x; 1.1136x over previous
#include <cuda_runtime.h>
#include <cuda_bf16.h>
#include <cstdint>

#define Tlen  8192
#define Bsz   4
#define RES   256
#define SKIPC 512
#define NCLSC 256
#define NLAY  30
#define WIN   3072
#define HSTR  3200

// ---------------- device scratch (allocation-free) ----------------
__device__ float g_h[2][Bsz][RES][HSTR];                 // ping-pong hidden state; pads zero
__device__ uint32_t g_Ad[(size_t)NLAY * 16 * 2 * 2 * 2048];  // conv A fragments  [lay][c32][s][hi/lo][2048]
__device__ uint32_t g_Ar[(size_t)NLAY * 8  * 2 * 2 * 2048];  // resid A fragments
__device__ float g_gLast[NLAY][Bsz][RES];
__device__ float g_skip[Bsz][SKIPC];

// ---------------- helpers ----------------
__device__ __forceinline__ uint32_t su32(const void* p) {
    return (uint32_t)__cvta_generic_to_shared(p);
}
__device__ __forceinline__ uint32_t pk2b(__nv_bfloat16 a, __nv_bfloat16 b) {
    __nv_bfloat162 v; v.x = a; v.y = b;
    return *(uint32_t*)&v;
}
__device__ __forceinline__ float gate_fn(float d) {
    float e1 = __expf(-d);
    float sg = __fdividef(1.f, 1.f + e1);
    float th = __fdividef(2.f, 1.f + e1 * e1) - 1.f;
    return th * sg;
}
__device__ __forceinline__ void hmma(float* d, const uint32_t* a, uint32_t b0, uint32_t b1) {
    asm volatile(
        "mma.sync.aligned.m16n8k16.row.col.f32.bf16.bf16.f32 "
        "{%0,%1,%2,%3}, {%4,%5,%6,%7}, {%8,%9}, {%0,%1,%2,%3};"
        : "+f"(d[0]), "+f"(d[1]), "+f"(d[2]), "+f"(d[3])
        : "r"(a[0]), "r"(a[1]), "r"(a[2]), "r"(a[3]), "r"(b0), "r"(b1));
}

#define CPA16(d, s) asm volatile("cp.async.cg.shared.global [%0],[%1],16;\n" :: "r"(d), "l"(s))
#define CPCOMMIT()  asm volatile("cp.async.commit_group;\n")
#define CPWAIT0()   asm volatile("cp.async.wait_group 0;\n" ::: "memory")

// ---------------- prep: weights -> bf16 hi/lo, A-fragment order ----------------
__global__ void prep_w(const float* __restrict__ W, uint32_t* __restrict__ dst, int conv) {
    int c16 = blockIdx.x, lay = blockIdx.y;
    int tid = threadIdx.x;
    int mt = tid >> 5, L = tid & 31, g = L >> 2, t = L & 3;
    uint32_t hi[4], lo[4];
#pragma unroll
    for (int r = 0; r < 4; r++) {
        int mm = mt * 16 + g + (r & 1) * 8;
        int kb = 2 * t + (r >> 1) * 8;
        float f0, f1;
        if (conv) {
            int tap = c16 >> 4;
            int ci  = (c16 & 15) * 16 + kb;
            const float* p = W + (((size_t)lay * 256 + mm) * 256 + ci) * 2 + tap;
            f0 = p[0]; f1 = p[2];
        } else {
            int k = c16 * 16 + kb;
            const float* p = W + ((size_t)lay * 256 + mm) * 256 + k;
            f0 = p[0]; f1 = p[1];
        }
        __nv_bfloat16 h0 = __float2bfloat16(f0), h1 = __float2bfloat16(f1);
        hi[r] = pk2b(h0, h1);
        lo[r] = pk2b(__float2bfloat16(f0 - __bfloat162float(h0)),
                     __float2bfloat16(f1 - __bfloat162float(h1)));
    }
    int K32 = conv ? 16 : 8;
    int c32 = c16 >> 1, s = c16 & 1;
    size_t base = ((((size_t)lay * K32 + c32) * 2 + s) * 2) * 2048 + (size_t)(mt * 32 + L) * 4;
#pragma unroll
    for (int r = 0; r < 4; r++) { dst[base + r] = hi[r]; dst[base + 2048 + r] = lo[r]; }
}

// ---------------- start conv ----------------
__global__ void start_conv(const float* __restrict__ x, const float* __restrict__ Wst,
                           const float* __restrict__ bst) {
    int b = blockIdx.y;
    int u = blockIdx.x * 256 + threadIdx.x;
    int t = (Tlen - WIN) + u;
    float x0 = x[b * Tlen + t - 1], x1 = x[b * Tlen + t];
    for (int c = 0; c < RES; c++)
        g_h[0][b][c][u] = bst[c] + Wst[2 * c] * x0 + Wst[2 * c + 1] * x1;
}

// ---------------- fused HMMA layer ----------------
// 512 thr = 16 warps: wr=warp>>2 (M 64-slice), wc=warp&3 (N slice of NT ntiles). BN = 32*NT.
// SEC = k32-sections per chunk (1 => k32 chunks, 2 => k64 chunks: half the barriers).
template <int NT, int SEC>
__global__ void __launch_bounds__(512, 1)
layer_mma(int pp, int layer, int dil, int u0,
          const uint32_t* __restrict__ Ac, const uint32_t* __restrict__ Ar,
          const float* __restrict__ bd, const float* __restrict__ br) {
    constexpr int NTB   = 4 * NT;
    constexpr int BN    = 8 * NTB;
    constexpr int NEL   = SEC * NT;            // B elements per thread per chunk
    constexpr int ASZ   = SEC * 8192;          // A u32 per chunk
    constexpr int BUFSZ = SEC * 256 * NTB;     // B u32 per chunk buffer
    constexpr int BSOFF = 2 * ASZ;
    constexpr int GSOFF = BSOFF + 2 * BUFSZ;
    constexpr int NCH1  = 16 / SEC;
    constexpr int NCH2  = 8 / SEC;

    extern __shared__ uint32_t sm[];
    const int tid = threadIdx.x, L = tid & 31, w = tid >> 5;
    const int wr = w >> 2, wc = w & 3, g = L >> 2, t = L & 3;
    const int b = blockIdx.y, ub = u0 + blockIdx.x * BN;

    const float* hin  = &g_h[pp][b][0][0];
    float*       hout = &g_h[pp ^ 1][b][0][0];

    float acc[4][NT][4];
#pragma unroll
    for (int mt = 0; mt < 4; mt++)
#pragma unroll
        for (int nl = 0; nl < NT; nl++)
#pragma unroll
            for (int e = 0; e < 4; e++) acc[mt][nl][e] = 0.f;

    float rb0[NEL], rb1[NEL];     // raw B values held across compute

    auto stageA = [&](int buf, const uint32_t* src) {   // ASZ u32 contiguous
        uint32_t* dstb = sm + buf * ASZ;
        for (int i = tid; i < ASZ / 4; i += 512)
            CPA16(su32(dstb + 4 * i), src + 4 * i);
    };
    // issue raw B global loads for conv chunk c (register destination, no stall)
    auto loadB = [&](int c) {
#pragma unroll
        for (int it = 0; it < NEL; it++) {
            int e = tid + it * 512;
            int LL = e & 31, x = e >> 5;
            int nt = x % NTB, y = x / NTB;
            int r = y & 1, s = (y >> 1) & 1, sec = y >> 2;
            int kk32 = c * SEC + sec;
            int tap = kk32 >> 3;
            int off = tap ? 0 : dil;
            int cibase = (kk32 * 32) & 255;
            int gg = LL >> 2, tt = LL & 3;
            int kk = 2 * tt + r * 8;
            int ci = cibase + s * 16 + kk;
            const float* p = hin + (size_t)ci * HSTR + (ub + nt * 8 + gg - off);
            rb0[it] = p[0];
            rb1[it] = p[HSTR];
        }
    };
    // convert held raw values -> bf16 hi/lo fragments (STS), data long arrived
    auto storeB = [&](int buf) {
#pragma unroll
        for (int it = 0; it < NEL; it++) {
            int e = tid + it * 512;
            int LL = e & 31, x = e >> 5;
            int nt = x % NTB, y = x / NTB;
            int r = y & 1, s = (y >> 1) & 1, sec = y >> 2;
            float f0 = rb0[it], f1 = rb1[it];
            __nv_bfloat16 h0 = __float2bfloat16(f0), h1 = __float2bfloat16(f1);
            int base = BSOFF + buf * BUFSZ;
            sm[base + ((((sec * 2 + s) * 2 + 0) * NTB + nt) * 32 + LL) * 2 + r] = pk2b(h0, h1);
            sm[base + ((((sec * 2 + s) * 2 + 1) * NTB + nt) * 32 + LL) * 2 + r] =
                pk2b(__float2bfloat16(f0 - __bfloat162float(h0)),
                     __float2bfloat16(f1 - __bfloat162float(h1)));
        }
    };

    // compute one chunk (SEC k32 sections); phase=0: B from staged buf, phase=1: B from gs
    auto compute = [&](int buf, int phase, int c) {
#pragma unroll
        for (int sec = 0; sec < SEC; sec++) {
#pragma unroll
            for (int s = 0; s < 2; s++) {
                uint4 ah[4], al[4];
                const uint32_t* Abase = sm + buf * ASZ + sec * 8192 + s * 4096;
#pragma unroll
                for (int mt = 0; mt < 4; mt++) {
                    int gmt = wr * 4 + mt;
                    ah[mt] = *(const uint4*)(Abase + (gmt * 32 + L) * 4);
                    al[mt] = *(const uint4*)(Abase + 2048 + (gmt * 32 + L) * 4);
                }
#pragma unroll
                for (int nl = 0; nl < NT; nl++) {
                    int nt = wc * NT + nl;
                    int ih, il;
                    if (phase == 0) {
                        int base = BSOFF + buf * BUFSZ;
                        ih = base + ((((sec * 2 + s) * 2 + 0) * NTB + nt) * 32 + L) * 2;
                        il = base + ((((sec * 2 + s) * 2 + 1) * NTB + nt) * 32 + L) * 2;
                    } else {
                        int kt = c * 2 * SEC + sec * 2 + s;
                        ih = GSOFF + ((((kt * 2 + 0) * NTB + nt) * 32 + L) * 2);
                        il = GSOFF + ((((kt * 2 + 1) * NTB + nt) * 32 + L) * 2);
                    }
                    uint32_t bh0 = sm[ih], bh1 = sm[ih + 1];
                    uint32_t bl0 = sm[il], bl1 = sm[il + 1];
#pragma unroll
                    for (int mt = 0; mt < 4; mt++) {
                        hmma(acc[mt][nl], (const uint32_t*)&ah[mt], bh0, bh1);
                        hmma(acc[mt][nl], (const uint32_t*)&al[mt], bh0, bh1);
                        hmma(acc[mt][nl], (const uint32_t*)&ah[mt], bl0, bl1);
                    }
                }
            }
        }
    };

    // ---- prologue: chunk 0 fully staged ----
    stageA(0, Ac); CPCOMMIT();
    loadB(0);
    storeB(0);            // one-time exposed latency
    int buf = 0;
    // ---- phase 1: conv GEMM ----
    for (int c = 0; c < NCH1; c++) {
        CPWAIT0(); __syncthreads();          // A(c) landed; B(c) STS visible
        if (c + 1 < NCH1) {
            loadB(c + 1);                    // issue LDGs now, consume after compute
            stageA(buf ^ 1, Ac + (size_t)(c + 1) * ASZ);
        } else {
            stageA(buf ^ 1, Ar);             // prefetch phase-2 chunk 0
        }
        CPCOMMIT();
        compute(buf, 0, c);                  // hides the B LDG latency
        if (c + 1 < NCH1) storeB(buf ^ 1);   // convert + STS (data arrived)
        buf ^= 1;
    }

    // ---- gate: acc -> gs (phase-2 B fragments, bf16 hi/lo) ----
#pragma unroll
    for (int mt = 0; mt < 4; mt++)
#pragma unroll
        for (int nl = 0; nl < NT; nl++)
#pragma unroll
            for (int e = 0; e < 4; e++) {
                int mm = wr * 64 + mt * 16 + g + (e >> 1) * 8;
                int n  = wc * NT * 8 + nl * 8 + 2 * t + (e & 1);
                float gv = gate_fn(acc[mt][nl][e] + bd[mm]);
                if (ub + n == WIN - 1) g_gLast[layer][b][mm] = gv;
                __nv_bfloat16 hh = __float2bfloat16(gv);
                __nv_bfloat16 ll = __float2bfloat16(gv - __bfloat162float(hh));
                int kt2 = mm >> 4, kk2 = mm & 15;
                int r2 = kk2 >> 3, t2 = (kk2 & 7) >> 1, hp = kk2 & 1;
                int L2 = (n & 7) * 4 + t2;
                int nt2 = n >> 3;
                int ih = GSOFF + ((((kt2 * 2 + 0) * NTB + nt2) * 32 + L2) * 2 + r2);
                int il = GSOFF + ((((kt2 * 2 + 1) * NTB + nt2) * 32 + L2) * 2 + r2);
                ((__nv_bfloat16*)&sm[ih])[hp] = hh;
                ((__nv_bfloat16*)&sm[il])[hp] = ll;
                acc[mt][nl][e] = 0.f;
            }

    // ---- phase 2: residual GEMM, B = gs ----
    for (int c = 0; c < NCH2; c++) {
        CPWAIT0(); __syncthreads();      // also publishes gs before first read
        if (c + 1 < NCH2) stageA(buf ^ 1, Ar + (size_t)(c + 1) * ASZ);
        CPCOMMIT();
        compute(buf, 1, c);
        buf ^= 1;
    }

    // ---- residual epilogue ----
#pragma unroll
    for (int mt = 0; mt < 4; mt++)
#pragma unroll
        for (int nl = 0; nl < NT; nl++)
#pragma unroll
            for (int e = 0; e < 4; e++) {
                int mm = wr * 64 + mt * 16 + g + (e >> 1) * 8;
                int n  = wc * NT * 8 + nl * 8 + 2 * t + (e & 1);
                int uu = ub + n;
                if (uu < WIN)
                    hout[(size_t)mm * HSTR + uu] =
                        hin[(size_t)mm * HSTR + uu] + acc[mt][nl][e] + br[mm];
            }
}

// ---------------- skip head ----------------
__global__ void skip_kernel(const float* __restrict__ Ws, const float* __restrict__ bs) {
    int b = blockIdx.x;
    int w = threadIdx.x >> 5, lane = threadIdx.x & 31;
    int so_base = blockIdx.y * 64 + w * 8;
    for (int oi = 0; oi < 8; oi++) {
        int so = so_base + oi;
        float v = (lane < NLAY) ? bs[lane * SKIPC + so] : 0.f;
        for (int l = 0; l < NLAY; l++) {
            const float* wr = Ws + ((size_t)l * SKIPC + so) * RES;
            const float* gg = &g_gLast[l][b][0];
#pragma unroll
            for (int k = lane; k < RES; k += 32) v += wr[k] * gg[k];
        }
#pragma unroll
        for (int s = 16; s; s >>= 1) v += __shfl_xor_sync(0xffffffffu, v, s);
        if (lane == 0) g_skip[b][so] = fmaxf(v, 0.f);
    }
}

// ---------------- end head ----------------
__global__ void end_kernel(const float* __restrict__ We1, const float* __restrict__ be1,
                           const float* __restrict__ We2, const float* __restrict__ be2,
                           float* __restrict__ out) {
    __shared__ float sk[SKIPC];
    __shared__ float mid[SKIPC];
    int b = blockIdx.x, tid = threadIdx.x;
    int w = tid >> 5, lane = tid & 31;
    for (int i = tid; i < SKIPC; i += 256) sk[i] = g_skip[b][i];
    __syncthreads();
    for (int oi = 0; oi < 64; oi++) {
        int so = w * 64 + oi;
        const float* row = We1 + (size_t)so * SKIPC;
        float v = 0.f;
#pragma unroll
        for (int k = lane; k < SKIPC; k += 32) v += row[k] * sk[k];
#pragma unroll
        for (int s = 16; s; s >>= 1) v += __shfl_xor_sync(0xffffffffu, v, s);
        if (lane == 0) mid[so] = fmaxf(v + be1[so], 0.f);
    }
    __syncthreads();
    for (int oi = 0; oi < 32; oi++) {
        int nc = w * 32 + oi;
        const float* row = We2 + (size_t)nc * SKIPC;
        float v = 0.f;
#pragma unroll
        for (int k = lane; k < SKIPC; k += 32) v += row[k] * mid[k];
#pragma unroll
        for (int s = 16; s; s >>= 1) v += __shfl_xor_sync(0xffffffffu, v, s);
        if (lane == 0) out[b * NCLSC + nc] = v + be2[nc];
    }
}

// ---------------- host ----------------
static const int DILS[NLAY] = {1,2,4,8,16,32,64,128,256,512,
                               1,2,4,8,16,32,64,128,256,512,
                               1,2,4,8,16,32,64,128,256,512};

static inline size_t smem_for(int NT, int SEC) {
    int NTB = 4 * NT;
    return (size_t)(2 * SEC * 8192 + 2 * SEC * 256 * NTB + 2048 * NTB) * 4;
}

extern "C" void kernel_launch(void* const* d_in, const int* in_sizes, int n_in,
                              void* d_out, int out_size) {
    (void)in_sizes; (void)n_in; (void)out_size;
    const float* x   = (const float*)d_in[0];
    const float* Wst = (const float*)d_in[1];
    const float* bst = (const float*)d_in[2];
    const float* Wd  = (const float*)d_in[3];
    const float* bd  = (const float*)d_in[4];
    const float* Wr  = (const float*)d_in[5];
    const float* br  = (const float*)d_in[6];
    const float* Ws  = (const float*)d_in[7];
    const float* bs  = (const float*)d_in[8];
    const float* We1 = (const float*)d_in[9];
    const float* be1 = (const float*)d_in[10];
    const float* We2 = (const float*)d_in[11];
    const float* be2 = (const float*)d_in[12];
    float* out = (float*)d_out;

    cudaFuncSetAttribute((const void*)layer_mma<3, 1>, cudaFuncAttributeMaxDynamicSharedMemorySize, (int)smem_for(3, 1));
    cudaFuncSetAttribute((const void*)layer_mma<2, 1>, cudaFuncAttributeMaxDynamicSharedMemorySize, (int)smem_for(2, 1));
    cudaFuncSetAttribute((const void*)layer_mma<1, 2>, cudaFuncAttributeMaxDynamicSharedMemorySize, (int)smem_for(1, 2));

    uint32_t *ad_dev, *ar_dev;
    cudaGetSymbolAddress((void**)&ad_dev, g_Ad);
    cudaGetSymbolAddress((void**)&ar_dev, g_Ar);

    prep_w<<<dim3(32, NLAY), 512>>>(Wd, ad_dev, 1);
    prep_w<<<dim3(16, NLAY), 512>>>(Wr, ar_dev, 0);
    start_conv<<<dim3(WIN / 256, Bsz), 256>>>(x, Wst, bst);

    int suf[NLAY + 1];
    suf[NLAY] = 0;
    for (int i = NLAY - 1; i >= 0; i--) suf[i] = suf[i + 1] + DILS[i];

    for (int i = 0; i < NLAY; i++) {
        int N  = 1 + suf[i + 1];
        int u0 = WIN - N;
        int pp = i & 1;
        const uint32_t* ac = ad_dev + (size_t)i * 16 * 8192;
        const uint32_t* ar = ar_dev + (size_t)i * 8 * 8192;
        const float* bdp = bd + (size_t)i * RES;
        const float* brp = br + (size_t)i * RES;

        if (N > 2368) {
            int gx = (N + 95) / 96;
            layer_mma<3, 1><<<dim3(gx, Bsz), 512, smem_for(3, 1)>>>(pp, i, DILS[i], u0, ac, ar, bdp, brp);
        } else if (N > 1184) {
            int gx = (N + 63) / 64;
            layer_mma<2, 1><<<dim3(gx, Bsz), 512, smem_for(2, 1)>>>(pp, i, DILS[i], u0, ac, ar, bdp, brp);
        } else {
            int gx = (N + 31) / 32;
            layer_mma<1, 2><<<dim3(gx, Bsz), 512, smem_for(1, 2)>>>(pp, i, DILS[i], u0, ac, ar, bdp, brp);
        }
    }

    skip_kernel<<<dim3(Bsz, SKIPC / 64), 256>>>(Ws, bs);
    end_kernel<<<Bsz, 256>>>(We1, be1, We2, be2, out);
}